// round 14
// baseline (speedup 1.0000x reference)
#include <cuda_runtime.h>
#include <math.h>
#include <stdint.h>

// Problem constants
#define BATCH   2
#define SEQ     2048
#define HID     1024
#define NHEADS  16
#define HDIM    64
#define MTOT    (BATCH*SEQ)          // 4096
#define QKV_N   (3*HID)              // 3072
#define LN_EPS  1e-5f

// ---- tf32 round helper (plain sm_80+ PTX, target-safe) ----
__device__ __forceinline__ float tf32r(float x) {
    uint32_t u;
    asm("cvt.rna.tf32.f32 %0, %1;" : "=r"(u) : "f"(x));
    return __uint_as_float(u);
}

// -------- scratch (static device arrays; no allocation allowed) --------
__device__ __align__(16) float g_q  [BATCH*NHEADS*SEQ*HDIM];  // [bh][s][d] tf32-rounded
__device__ __align__(16) float g_k  [BATCH*NHEADS*SEQ*HDIM];  // [bh][s][d] tf32-rounded
__device__ __align__(16) float g_v  [BATCH*NHEADS*HDIM*SEQ];  // [bh][d][s] TRANSPOSED, tf32-rounded
__device__ __align__(16) float g_ao [BATCH*SEQ*HID];          // tf32-rounded at write
__device__ __align__(16) float g_xc [MTOT*HID];               // tf32-rounded X
__device__ __align__(16) float g_wtA[QKV_N*HID];              // W_attn^T, tf32-rounded
__device__ __align__(16) float g_wtP[HID*HID];                // W_proj^T, tf32-rounded

// ---- misc PTX helpers ----
__device__ __forceinline__ uint32_t smem_u32(const void* p) {
    uint32_t a;
    asm("{ .reg .u64 t; cvta.to.shared.u64 t, %1; cvt.u32.u64 %0, t; }"
        : "=r"(a) : "l"(p));
    return a;
}
__device__ __forceinline__ void cp_async16(uint32_t dst, const void* src) {
    asm volatile("cp.async.cg.shared.global [%0], [%1], 16;" :: "r"(dst), "l"(src));
}
__device__ __forceinline__ void cp_commit() { asm volatile("cp.async.commit_group;" ::: "memory"); }
template<int N> __device__ __forceinline__ void cp_wait() {
    asm volatile("cp.async.wait_group %0;" :: "n"(N) : "memory");
}

#define MMA_TF32(ACC, A0,A1,A2,A3, B0,B1) \
    asm volatile("mma.sync.aligned.m16n8k8.row.col.f32.tf32.tf32.f32 " \
        "{%0,%1,%2,%3}, {%4,%5,%6,%7}, {%8,%9}, {%0,%1,%2,%3};" \
        : "+f"((ACC)[0]), "+f"((ACC)[1]), "+f"((ACC)[2]), "+f"((ACC)[3]) \
        : "r"(A0), "r"(A1), "r"(A2), "r"(A3), "r"(B0), "r"(B1))

// FMA-pipe exp: p = exp(s*0.125 - 8) = 2^(s*C1 + C0). No MUFU.
__device__ __forceinline__ float fexp_s(float s) {
    const float C1 = 0.1803368801111737f;    //  0.125*log2(e)
    const float C0 = -11.541560327111707f;   // -8*log2(e)
    float z = fmaf(s, C1, C0);
    float t = z + 12582912.0f;               // round-to-nearest int (magic)
    float nf = t - 12582912.0f;
    float f = z - nf;                        // f in [-0.5, 0.5]
    float q = fmaf(1.33335581e-3f, f, 9.61812910e-3f);
    q = fmaf(q, f, 5.55041087e-2f);
    q = fmaf(q, f, 2.40226507e-1f);
    q = fmaf(q, f, 6.93147181e-1f);
    q = fmaf(q, f, 1.0f);
    int n = __float_as_int(t) - 0x4B400000;
    return __int_as_float(__float_as_int(q) + (n << 23));
}

// ============================================================================
// Elementwise tf32 rounding (X input)
// ============================================================================
__global__ __launch_bounds__(256)
void cvt_tf32_kernel(const float* __restrict__ in, float* __restrict__ out)
{
    int i = blockIdx.x*256 + threadIdx.x;
    float4 v = ((const float4*)in)[i];
    v.x = tf32r(v.x); v.y = tf32r(v.y); v.z = tf32r(v.z); v.w = tf32r(v.w);
    ((float4*)out)[i] = v;
}

// ============================================================================
// Transpose + tf32 round: out[n][Kdim] = tf32(in[k][Ndim])
// ============================================================================
__global__ __launch_bounds__(256)
void transpose_kernel(const float* __restrict__ in, float* __restrict__ out,
                      int Kdim, int Ndim)
{
    __shared__ float tile[32][33];
    const int n0 = blockIdx.x*32, k0 = blockIdx.y*32;
    const int tx = threadIdx.x, ty = threadIdx.y;
    #pragma unroll
    for (int i = ty; i < 32; i += 8)
        tile[i][tx] = in[(k0+i)*Ndim + n0 + tx];
    __syncthreads();
    #pragma unroll
    for (int i = ty; i < 32; i += 8)
        out[(n0+i)*Kdim + k0 + tx] = tf32r(tile[tx][i]);
}

// ============================================================================
// TF32 mma.sync GEMM (unchanged from R13). mode 0: plain epilogue.
// mode 1: QKV epilogue — QK LayerNorm, tf32 rounding, V transposed scatter.
// ============================================================================
#define BK 32
#define AST 36
#define HALF_STG (128*AST*4)
#define STG_BYTES (2*HALF_STG)
#define DYN_SMEM (2*STG_BYTES)

__global__ __launch_bounds__(256, 2)
void gemm_mma_kernel(const float* __restrict__ A,
                     const float* __restrict__ Bt,
                     const float* __restrict__ bias,
                     const float* __restrict__ qg, const float* __restrict__ qb,
                     const float* __restrict__ kg, const float* __restrict__ kb,
                     float* __restrict__ outp, int Ng, int mode)
{
    extern __shared__ char smem[];
    const uint32_t sb = smem_u32(smem);
    const int tid = threadIdx.x;
    const int wid = tid >> 5, lane = tid & 31;
    const int g = lane >> 2, tg = lane & 3;
    const int wy = wid >> 2, wx = wid & 3;
    const int row0 = blockIdx.y * 128;
    const int col0 = blockIdx.x * 128;

    float acc[4][4][4];
    #pragma unroll
    for (int mi = 0; mi < 4; mi++)
        #pragma unroll
        for (int ni = 0; ni < 4; ni++)
            #pragma unroll
            for (int e = 0; e < 4; e++) acc[mi][ni][e] = 0.f;

    auto load_chunk = [&](int c, int s) {
        const uint32_t ab = sb + s*STG_BYTES;
        const uint32_t bb = ab + HALF_STG;
        const int kk = c * BK;
        #pragma unroll
        for (int i = 0; i < 4; i++) {
            int idx = tid + 256*i;
            int m = idx >> 3, kq = idx & 7;
            cp_async16(ab + m*(AST*4) + kq*16,
                       &A[(size_t)(row0 + m)*HID + kk + kq*4]);
        }
        #pragma unroll
        for (int i = 0; i < 4; i++) {
            int idx = tid + 256*i;
            int n = idx >> 3, kq = idx & 7;
            cp_async16(bb + n*(AST*4) + kq*16,
                       &Bt[(size_t)(col0 + n)*HID + kk + kq*4]);
        }
        cp_commit();
    };

    load_chunk(0, 0);
    load_chunk(1, 1);

    const int NC = HID / BK;
    for (int c = 0; c < NC; c++) {
        const int s = c & 1;
        if (c + 1 < NC) cp_wait<1>(); else cp_wait<0>();
        __syncthreads();
        const float* Asf = (const float*)(smem + s*STG_BYTES);
        const float* Bsf = Asf + 128*AST;

        #pragma unroll
        for (int ks = 0; ks < 4; ks++) {
            const int kb2 = ks * 8;
            uint32_t a[4][4], b[4][2];
            #pragma unroll
            for (int mi = 0; mi < 4; mi++) {
                const int r = wy*64 + mi*16;
                a[mi][0] = __float_as_uint(Asf[(r+g  )*AST + kb2+tg  ]);
                a[mi][1] = __float_as_uint(Asf[(r+g+8)*AST + kb2+tg  ]);
                a[mi][2] = __float_as_uint(Asf[(r+g  )*AST + kb2+tg+4]);
                a[mi][3] = __float_as_uint(Asf[(r+g+8)*AST + kb2+tg+4]);
            }
            #pragma unroll
            for (int ni = 0; ni < 4; ni++) {
                const int n0 = wx*32 + ni*8;
                b[ni][0] = __float_as_uint(Bsf[(n0+g)*AST + kb2+tg  ]);
                b[ni][1] = __float_as_uint(Bsf[(n0+g)*AST + kb2+tg+4]);
            }
            #pragma unroll
            for (int mi = 0; mi < 4; mi++)
                #pragma unroll
                for (int ni = 0; ni < 4; ni++)
                    MMA_TF32(acc[mi][ni], a[mi][0], a[mi][1], a[mi][2], a[mi][3],
                             b[ni][0], b[ni][1]);
        }
        __syncthreads();
        if (c + 2 < NC) load_chunk(c + 2, s);
    }

    // stage accumulators to SMEM
    float* sOut = (float*)smem;
    #pragma unroll
    for (int mi = 0; mi < 4; mi++)
        #pragma unroll
        for (int ni = 0; ni < 4; ni++) {
            const int r0 = wy*64 + mi*16 + g;
            const int c0 = wx*32 + ni*8 + 2*tg;
            *(float2*)&sOut[ r0   *132 + c0] = make_float2(acc[mi][ni][0], acc[mi][ni][1]);
            *(float2*)&sOut[(r0+8)*132 + c0] = make_float2(acc[mi][ni][2], acc[mi][ni][3]);
        }
    __syncthreads();

    const int r = tid >> 1, half = tid & 1;
    const int grow = row0 + r;
    __align__(16) float cf[64];
    #pragma unroll
    for (int e = 0; e < 16; e++)
        ((float4*)cf)[e] = *(float4*)&sOut[r*132 + half*64 + e*4];
    const int nb = col0 + half*64;
    #pragma unroll
    for (int d = 0; d < 64; d++) cf[d] += bias[nb + d];

    if (mode == 0) {
        float4* op = (float4*)&outp[(size_t)grow*Ng + nb];
        #pragma unroll
        for (int e = 0; e < 16; e++) op[e] = ((float4*)cf)[e];
    } else {
        const int colhalf = blockIdx.x*2 + half;
        const int part = colhalf >> 4;             // 0=q 1=k 2=v
        const int head = colhalf & 15;
        const int b = grow >> 11, sidx = grow & 2047;
        if (part == 2) {
            // V: transposed scatter [bh][d][s], tf32-rounded
            float* dv = &g_v[((size_t)(b*NHEADS + head)*HDIM)*SEQ + sidx];
            #pragma unroll
            for (int d = 0; d < 64; d++) dv[(size_t)d*SEQ] = tf32r(cf[d]);
        } else {
            float mu = 0.f;
            #pragma unroll
            for (int d = 0; d < 64; d++) mu += cf[d];
            mu *= (1.0f/64.0f);
            float var = 0.f;
            #pragma unroll
            for (int d = 0; d < 64; d++) { float df = cf[d]-mu; var += df*df; }
            var *= (1.0f/64.0f);
            const float rs = rsqrtf(var + LN_EPS);
            const float* ga = (part == 0) ? qg : kg;
            const float* be = (part == 0) ? qb : kb;
            #pragma unroll
            for (int d = 0; d < 64; d++)
                cf[d] = tf32r((cf[d]-mu)*rs*ga[d] + be[d]);
            float* dst = (part == 0) ? g_q : g_k;
            float4* op = (float4*)&dst[(size_t)((b*NHEADS + head)*SEQ + sidx)*HDIM];
            #pragma unroll
            for (int e = 0; e < 16; e++) op[e] = ((float4*)cf)[e];
        }
    }
}

// ============================================================================
// Causal flash attention with mma.sync tf32 — fused per-ni pipeline.
// Block: 128 q-rows x 1 head, 8 warps; warp owns 16 rows x 64 cols.
// Per key-tile: for each ni: QK(ni) -> exp -> shfl C->A transform -> PV(ni).
// No Pt SMEM buffer, no mid-tile syncwarp. smem 69.6KB -> 3 CTAs/SM.
// Arithmetic order identical to R13 (rel_err preserved).
// ============================================================================
#define KST 68
#define KS_OFF(s)  ((s)*4352)
#define VS_OFF(s)  (8704 + (s)*4352)
#define ATT_SMEM   (17408*4)   // 69632 B

__global__ __launch_bounds__(256, 3)
void attn_mma_kernel()
{
    extern __shared__ float sm[];
    const int tid = threadIdx.x, wid = tid >> 5, lane = tid & 31;
    const int g = lane >> 2, tg = lane & 3;
    const int qt = 15 - (int)blockIdx.x;     // heavy first
    const int bh = blockIdx.y;
    const int ktmax = 2*qt + 1;

    const int qrow_lo = qt*128 + wid*16 + g;
    const int qrow_hi = qrow_lo + 8;

    // Q fragments: 32 loads, one-time
    const float* Qb = &g_q[(size_t)(bh*SEQ)*HDIM];
    uint32_t aQ[8][4];
    #pragma unroll
    for (int ks = 0; ks < 8; ks++) {
        aQ[ks][0] = __float_as_uint(Qb[qrow_lo*64 + ks*8 + tg  ]);
        aQ[ks][1] = __float_as_uint(Qb[qrow_hi*64 + ks*8 + tg  ]);
        aQ[ks][2] = __float_as_uint(Qb[qrow_lo*64 + ks*8 + tg+4]);
        aQ[ks][3] = __float_as_uint(Qb[qrow_hi*64 + ks*8 + tg+4]);
    }

    float O[8][4];
    #pragma unroll
    for (int nj = 0; nj < 8; nj++)
        #pragma unroll
        for (int e = 0; e < 4; e++) O[nj][e] = 0.f;
    float l_lo = 0.f, l_hi = 0.f;

    const float* Kg = &g_k[(size_t)(bh*SEQ)*HDIM];
    const float* Vg = &g_v[(size_t)(bh*HDIM)*SEQ];   // [d][s]

    // FULL-tile prefetch: 64 rows x 16 float4-cols per tensor.
    auto prefetch = [&](int kt) {
        const int s = kt & 1;
        #pragma unroll
        for (int i = 0; i < 4; i++) {
            int idx = tid + 256*i;
            int row = idx >> 4, cq = idx & 15;
            cp_async16(smem_u32(sm + KS_OFF(s) + row*KST + cq*4),
                       Kg + (size_t)(kt*64 + row)*64 + cq*4);
        }
        #pragma unroll
        for (int i = 0; i < 4; i++) {
            int idx = tid + 256*i;
            int row = idx >> 4, cq = idx & 15;
            cp_async16(smem_u32(sm + VS_OFF(s) + row*KST + cq*4),
                       Vg + (size_t)row*SEQ + kt*64 + cq*4);
        }
        cp_commit();
    };

    prefetch(0);

    const int srcA = (lane & ~3) | (tg >> 1);
    const int srcB = srcA + 2;
    const bool odd = (tg & 1);

    for (int kt = 0; kt <= ktmax; kt++) {
        cp_wait<0>();
        __syncthreads();
        if (kt < ktmax) prefetch(kt + 1);

        const int jb = kt*64;
        if (jb <= qt*128 + wid*16 + 15) {   // warp-uniform: any row unmasked?
            const float* Ksm = sm + KS_OFF(kt & 1);
            const float* Vsm = sm + VS_OFF(kt & 1);

            #pragma unroll
            for (int ni = 0; ni < 8; ni++) {
                // ---- QK^T for this 8-key block ----
                float S[4] = {0.f, 0.f, 0.f, 0.f};
                const int n0 = ni*8 + g;
                #pragma unroll
                for (int ks = 0; ks < 8; ks++) {
                    uint32_t b0 = __float_as_uint(Ksm[n0*KST + ks*8 + tg  ]);
                    uint32_t b1 = __float_as_uint(Ksm[n0*KST + ks*8 + tg+4]);
                    MMA_TF32(S, aQ[ks][0], aQ[ks][1], aQ[ks][2], aQ[ks][3], b0, b1);
                }

                // ---- mask + exp (FMA pipe) + tf32 round ----
                const int j0 = jb + ni*8 + 2*tg;
                float p0 = (j0     <= qrow_lo) ? tf32r(fexp_s(S[0])) : 0.f;
                float p1 = (j0 + 1 <= qrow_lo) ? tf32r(fexp_s(S[1])) : 0.f;
                float p2 = (j0     <= qrow_hi) ? tf32r(fexp_s(S[2])) : 0.f;
                float p3 = (j0 + 1 <= qrow_hi) ? tf32r(fexp_s(S[3])) : 0.f;
                l_lo += p0 + p1;
                l_hi += p2 + p3;

                // ---- C-layout -> A-layout via intra-quad shuffles ----
                float x0, x1;
                x0 = __shfl_sync(0xFFFFFFFFu, p0, srcA);
                x1 = __shfl_sync(0xFFFFFFFFu, p1, srcA);
                uint32_t a0 = __float_as_uint(odd ? x1 : x0);   // P[g][tg]
                x0 = __shfl_sync(0xFFFFFFFFu, p2, srcA);
                x1 = __shfl_sync(0xFFFFFFFFu, p3, srcA);
                uint32_t a1 = __float_as_uint(odd ? x1 : x0);   // P[g+8][tg]
                x0 = __shfl_sync(0xFFFFFFFFu, p0, srcB);
                x1 = __shfl_sync(0xFFFFFFFFu, p1, srcB);
                uint32_t a2 = __float_as_uint(odd ? x1 : x0);   // P[g][tg+4]
                x0 = __shfl_sync(0xFFFFFFFFu, p2, srcB);
                x1 = __shfl_sync(0xFFFFFFFFu, p3, srcB);
                uint32_t a3 = __float_as_uint(odd ? x1 : x0);   // P[g+8][tg+4]

                // ---- P @ V for this 8-key block ----
                #pragma unroll
                for (int nj = 0; nj < 8; nj++) {
                    const int m0 = nj*8 + g;
                    uint32_t b0 = __float_as_uint(Vsm[m0*KST + ni*8 + tg  ]);
                    uint32_t b1 = __float_as_uint(Vsm[m0*KST + ni*8 + tg+4]);
                    MMA_TF32(O[nj], a0, a1, a2, a3, b0, b1);
                }
            }
        }
    }

    // ---- epilogue: normalize, stage (reuse K/V smem), coalesced write ----
    l_lo += __shfl_xor_sync(0xFFFFFFFFu, l_lo, 1);
    l_lo += __shfl_xor_sync(0xFFFFFFFFu, l_lo, 2);
    l_hi += __shfl_xor_sync(0xFFFFFFFFu, l_hi, 1);
    l_hi += __shfl_xor_sync(0xFFFFFFFFu, l_hi, 2);
    const float inv_lo = 1.0f / l_lo;
    const float inv_hi = 1.0f / l_hi;

    __syncthreads();   // all warps done reading K/V smem
    float* Ow = sm + wid*1088;   // [16][KST] per warp, inside K/V region
    #pragma unroll
    for (int nj = 0; nj < 8; nj++) {
        const int c0 = nj*8 + 2*tg;
        *(float2*)&Ow[ g   *KST + c0] = make_float2(O[nj][0]*inv_lo, O[nj][1]*inv_lo);
        *(float2*)&Ow[(g+8)*KST + c0] = make_float2(O[nj][2]*inv_hi, O[nj][3]*inv_hi);
    }
    __syncthreads();

    const int r = tid >> 1, half = tid & 1;
    const float* src = sm + (r >> 4)*1088 + (r & 15)*KST + half*32;
    const int grow = qt*128 + r;
    const int b = bh >> 4, h = bh & 15;
    float* dst = &g_ao[((size_t)(b*SEQ + grow))*HID + h*64 + half*32];
    #pragma unroll
    for (int e = 0; e < 8; e++) {
        float4 v = *(const float4*)&src[e*4];
        v.x = tf32r(v.x); v.y = tf32r(v.y); v.z = tf32r(v.z); v.w = tf32r(v.w);
        ((float4*)dst)[e] = v;
    }
}

// ============================================================================
// launch
// ============================================================================
extern "C" void kernel_launch(void* const* d_in, const int* in_sizes, int n_in,
                              void* d_out, int out_size)
{
    const float* X      = (const float*)d_in[0];
    const float* W_attn = (const float*)d_in[1];
    const float* b_attn = (const float*)d_in[2];
    const float* W_proj = (const float*)d_in[3];
    const float* b_proj = (const float*)d_in[4];
    const float* qg     = (const float*)d_in[5];
    const float* qb     = (const float*)d_in[6];
    const float* kg     = (const float*)d_in[7];
    const float* kb     = (const float*)d_in[8];
    float* out = (float*)d_out;

    cudaFuncSetAttribute(gemm_mma_kernel,
                         cudaFuncAttributeMaxDynamicSharedMemorySize, DYN_SMEM);
    cudaFuncSetAttribute(attn_mma_kernel,
                         cudaFuncAttributeMaxDynamicSharedMemorySize, ATT_SMEM);

    float* wtA; cudaGetSymbolAddress((void**)&wtA, g_wtA);
    float* wtP; cudaGetSymbolAddress((void**)&wtP, g_wtP);
    float* xc;  cudaGetSymbolAddress((void**)&xc,  g_xc);
    float* ao;  cudaGetSymbolAddress((void**)&ao,  g_ao);

    cvt_tf32_kernel<<<MTOT*HID/1024, 256>>>(X, xc);
    transpose_kernel<<<dim3(QKV_N/32, HID/32), dim3(32,8)>>>(W_attn, wtA, HID, QKV_N);
    transpose_kernel<<<dim3(HID/32,  HID/32), dim3(32,8)>>>(W_proj, wtP, HID, HID);

    gemm_mma_kernel<<<dim3(QKV_N/128, MTOT/128), 256, DYN_SMEM>>>(
        xc, wtA, b_attn, qg, qb, kg, kb, nullptr, QKV_N, 1);

    attn_mma_kernel<<<dim3(16, BATCH*NHEADS), 256, ATT_SMEM>>>();

    gemm_mma_kernel<<<dim3(HID/128, MTOT/128), 256, DYN_SMEM>>>(
        ao, wtP, b_proj, qg, qb, kg, kb, out, HID, 0);
}

// round 16
// speedup vs baseline: 1.0339x; 1.0339x over previous
#include <cuda_runtime.h>
#include <math.h>
#include <stdint.h>

// Problem constants
#define BATCH   2
#define SEQ     2048
#define HID     1024
#define NHEADS  16
#define HDIM    64
#define MTOT    (BATCH*SEQ)          // 4096
#define QKV_N   (3*HID)              // 3072
#define LN_EPS  1e-5f

// ---- tf32 round helper (plain sm_80+ PTX, target-safe) ----
__device__ __forceinline__ float tf32r(float x) {
    uint32_t u;
    asm("cvt.rna.tf32.f32 %0, %1;" : "=r"(u) : "f"(x));
    return __uint_as_float(u);
}

// -------- scratch (static device arrays; no allocation allowed) --------
__device__ __align__(16) float g_q  [BATCH*NHEADS*SEQ*HDIM];  // [bh][s][d] tf32-rounded
__device__ __align__(16) float g_k  [BATCH*NHEADS*SEQ*HDIM];  // [bh][s][d] tf32-rounded
__device__ __align__(16) float g_v  [BATCH*NHEADS*HDIM*SEQ];  // [bh][d][s] TRANSPOSED, tf32-rounded
__device__ __align__(16) float g_ao [BATCH*SEQ*HID];          // tf32-rounded at write
__device__ __align__(16) float g_xc [MTOT*HID];               // tf32-rounded X
__device__ __align__(16) float g_wtA[QKV_N*HID];              // W_attn^T, tf32-rounded
__device__ __align__(16) float g_wtP[HID*HID];                // W_proj^T, tf32-rounded

// ---- misc PTX helpers ----
__device__ __forceinline__ uint32_t smem_u32(const void* p) {
    uint32_t a;
    asm("{ .reg .u64 t; cvta.to.shared.u64 t, %1; cvt.u32.u64 %0, t; }"
        : "=r"(a) : "l"(p));
    return a;
}
__device__ __forceinline__ void cp_async16(uint32_t dst, const void* src) {
    asm volatile("cp.async.cg.shared.global [%0], [%1], 16;" :: "r"(dst), "l"(src));
}
__device__ __forceinline__ void cp_commit() { asm volatile("cp.async.commit_group;" ::: "memory"); }
template<int N> __device__ __forceinline__ void cp_wait() {
    asm volatile("cp.async.wait_group %0;" :: "n"(N) : "memory");
}

#define MMA_TF32(ACC, A0,A1,A2,A3, B0,B1) \
    asm volatile("mma.sync.aligned.m16n8k8.row.col.f32.tf32.tf32.f32 " \
        "{%0,%1,%2,%3}, {%4,%5,%6,%7}, {%8,%9}, {%0,%1,%2,%3};" \
        : "+f"((ACC)[0]), "+f"((ACC)[1]), "+f"((ACC)[2]), "+f"((ACC)[3]) \
        : "r"(A0), "r"(A1), "r"(A2), "r"(A3), "r"(B0), "r"(B1))

// FMA-pipe exp: p = exp(s*0.125 - 8) = 2^(s*C1 + C0). No MUFU.
__device__ __forceinline__ float fexp_s(float s) {
    const float C1 = 0.1803368801111737f;    //  0.125*log2(e)
    const float C0 = -11.541560327111707f;   // -8*log2(e)
    float z = fmaf(s, C1, C0);
    float t = z + 12582912.0f;               // round-to-nearest int (magic)
    float nf = t - 12582912.0f;
    float f = z - nf;                        // f in [-0.5, 0.5]
    float q = fmaf(1.33335581e-3f, f, 9.61812910e-3f);
    q = fmaf(q, f, 5.55041087e-2f);
    q = fmaf(q, f, 2.40226507e-1f);
    q = fmaf(q, f, 6.93147181e-1f);
    q = fmaf(q, f, 1.0f);
    int n = __float_as_int(t) - 0x4B400000;
    return __int_as_float(__float_as_int(q) + (n << 23));
}

// ============================================================================
// Elementwise tf32 rounding (X input)
// ============================================================================
__global__ __launch_bounds__(256)
void cvt_tf32_kernel(const float* __restrict__ in, float* __restrict__ out)
{
    int i = blockIdx.x*256 + threadIdx.x;
    float4 v = ((const float4*)in)[i];
    v.x = tf32r(v.x); v.y = tf32r(v.y); v.z = tf32r(v.z); v.w = tf32r(v.w);
    ((float4*)out)[i] = v;
}

// ============================================================================
// Transpose + tf32 round: out[n][Kdim] = tf32(in[k][Ndim])
// ============================================================================
__global__ __launch_bounds__(256)
void transpose_kernel(const float* __restrict__ in, float* __restrict__ out,
                      int Kdim, int Ndim)
{
    __shared__ float tile[32][33];
    const int n0 = blockIdx.x*32, k0 = blockIdx.y*32;
    const int tx = threadIdx.x, ty = threadIdx.y;
    #pragma unroll
    for (int i = ty; i < 32; i += 8)
        tile[i][tx] = in[(k0+i)*Ndim + n0 + tx];
    __syncthreads();
    #pragma unroll
    for (int i = ty; i < 32; i += 8)
        out[(n0+i)*Kdim + k0 + tx] = tf32r(tile[tx][i]);
}

// ============================================================================
// TF32 mma.sync GEMM (unchanged from R13). mode 0: plain epilogue.
// mode 1: QKV epilogue — QK LayerNorm, tf32 rounding, V transposed scatter.
// ============================================================================
#define BK 32
#define AST 36
#define HALF_STG (128*AST*4)
#define STG_BYTES (2*HALF_STG)
#define DYN_SMEM (2*STG_BYTES)

__global__ __launch_bounds__(256, 2)
void gemm_mma_kernel(const float* __restrict__ A,
                     const float* __restrict__ Bt,
                     const float* __restrict__ bias,
                     const float* __restrict__ qg, const float* __restrict__ qb,
                     const float* __restrict__ kg, const float* __restrict__ kb,
                     float* __restrict__ outp, int Ng, int mode)
{
    extern __shared__ char smem[];
    const uint32_t sb = smem_u32(smem);
    const int tid = threadIdx.x;
    const int wid = tid >> 5, lane = tid & 31;
    const int g = lane >> 2, tg = lane & 3;
    const int wy = wid >> 2, wx = wid & 3;
    const int row0 = blockIdx.y * 128;
    const int col0 = blockIdx.x * 128;

    float acc[4][4][4];
    #pragma unroll
    for (int mi = 0; mi < 4; mi++)
        #pragma unroll
        for (int ni = 0; ni < 4; ni++)
            #pragma unroll
            for (int e = 0; e < 4; e++) acc[mi][ni][e] = 0.f;

    auto load_chunk = [&](int c, int s) {
        const uint32_t ab = sb + s*STG_BYTES;
        const uint32_t bb = ab + HALF_STG;
        const int kk = c * BK;
        #pragma unroll
        for (int i = 0; i < 4; i++) {
            int idx = tid + 256*i;
            int m = idx >> 3, kq = idx & 7;
            cp_async16(ab + m*(AST*4) + kq*16,
                       &A[(size_t)(row0 + m)*HID + kk + kq*4]);
        }
        #pragma unroll
        for (int i = 0; i < 4; i++) {
            int idx = tid + 256*i;
            int n = idx >> 3, kq = idx & 7;
            cp_async16(bb + n*(AST*4) + kq*16,
                       &Bt[(size_t)(col0 + n)*HID + kk + kq*4]);
        }
        cp_commit();
    };

    load_chunk(0, 0);
    load_chunk(1, 1);

    const int NC = HID / BK;
    for (int c = 0; c < NC; c++) {
        const int s = c & 1;
        if (c + 1 < NC) cp_wait<1>(); else cp_wait<0>();
        __syncthreads();
        const float* Asf = (const float*)(smem + s*STG_BYTES);
        const float* Bsf = Asf + 128*AST;

        #pragma unroll
        for (int ks = 0; ks < 4; ks++) {
            const int kb2 = ks * 8;
            uint32_t a[4][4], b[4][2];
            #pragma unroll
            for (int mi = 0; mi < 4; mi++) {
                const int r = wy*64 + mi*16;
                a[mi][0] = __float_as_uint(Asf[(r+g  )*AST + kb2+tg  ]);
                a[mi][1] = __float_as_uint(Asf[(r+g+8)*AST + kb2+tg  ]);
                a[mi][2] = __float_as_uint(Asf[(r+g  )*AST + kb2+tg+4]);
                a[mi][3] = __float_as_uint(Asf[(r+g+8)*AST + kb2+tg+4]);
            }
            #pragma unroll
            for (int ni = 0; ni < 4; ni++) {
                const int n0 = wx*32 + ni*8;
                b[ni][0] = __float_as_uint(Bsf[(n0+g)*AST + kb2+tg  ]);
                b[ni][1] = __float_as_uint(Bsf[(n0+g)*AST + kb2+tg+4]);
            }
            #pragma unroll
            for (int mi = 0; mi < 4; mi++)
                #pragma unroll
                for (int ni = 0; ni < 4; ni++)
                    MMA_TF32(acc[mi][ni], a[mi][0], a[mi][1], a[mi][2], a[mi][3],
                             b[ni][0], b[ni][1]);
        }
        __syncthreads();
        if (c + 2 < NC) load_chunk(c + 2, s);
    }

    // stage accumulators to SMEM
    float* sOut = (float*)smem;
    #pragma unroll
    for (int mi = 0; mi < 4; mi++)
        #pragma unroll
        for (int ni = 0; ni < 4; ni++) {
            const int r0 = wy*64 + mi*16 + g;
            const int c0 = wx*32 + ni*8 + 2*tg;
            *(float2*)&sOut[ r0   *132 + c0] = make_float2(acc[mi][ni][0], acc[mi][ni][1]);
            *(float2*)&sOut[(r0+8)*132 + c0] = make_float2(acc[mi][ni][2], acc[mi][ni][3]);
        }
    __syncthreads();

    const int r = tid >> 1, half = tid & 1;
    const int grow = row0 + r;
    __align__(16) float cf[64];
    #pragma unroll
    for (int e = 0; e < 16; e++)
        ((float4*)cf)[e] = *(float4*)&sOut[r*132 + half*64 + e*4];
    const int nb = col0 + half*64;
    #pragma unroll
    for (int d = 0; d < 64; d++) cf[d] += bias[nb + d];

    if (mode == 0) {
        float4* op = (float4*)&outp[(size_t)grow*Ng + nb];
        #pragma unroll
        for (int e = 0; e < 16; e++) op[e] = ((float4*)cf)[e];
    } else {
        const int colhalf = blockIdx.x*2 + half;
        const int part = colhalf >> 4;             // 0=q 1=k 2=v
        const int head = colhalf & 15;
        const int b = grow >> 11, sidx = grow & 2047;
        if (part == 2) {
            // V: transposed scatter [bh][d][s], tf32-rounded
            float* dv = &g_v[((size_t)(b*NHEADS + head)*HDIM)*SEQ + sidx];
            #pragma unroll
            for (int d = 0; d < 64; d++) dv[(size_t)d*SEQ] = tf32r(cf[d]);
        } else {
            float mu = 0.f;
            #pragma unroll
            for (int d = 0; d < 64; d++) mu += cf[d];
            mu *= (1.0f/64.0f);
            float var = 0.f;
            #pragma unroll
            for (int d = 0; d < 64; d++) { float df = cf[d]-mu; var += df*df; }
            var *= (1.0f/64.0f);
            const float rs = rsqrtf(var + LN_EPS);
            const float* ga = (part == 0) ? qg : kg;
            const float* be = (part == 0) ? qb : kb;
            #pragma unroll
            for (int d = 0; d < 64; d++)
                cf[d] = tf32r((cf[d]-mu)*rs*ga[d] + be[d]);
            float* dst = (part == 0) ? g_q : g_k;
            float4* op = (float4*)&dst[(size_t)((b*NHEADS + head)*SEQ + sidx)*HDIM];
            #pragma unroll
            for (int e = 0; e < 16; e++) op[e] = ((float4*)cf)[e];
        }
    }
}

// ============================================================================
// Causal flash attention with mma.sync tf32 — fused per-ni pipeline.
// Block: 128 q-rows x 1 head, 8 warps; warp owns 16 rows x 64 cols.
// Per key-tile: for each ni: QK(ni) -> exp -> shfl C->A transform -> PV(ni).
// No Pt SMEM buffer, no mid-tile syncwarp.
// CHANGE vs R14: __launch_bounds__(256, 2) — 128 regs, NO SPILLS (R14's
// (256,3) capped regs at 85 and spilled the fragment arrays to local).
// Arithmetic order identical to R13/R14 (rel_err preserved).
// ============================================================================
#define KST 68
#define KS_OFF(s)  ((s)*4352)
#define VS_OFF(s)  (8704 + (s)*4352)
#define ATT_SMEM   (17408*4)   // 69632 B

__global__ __launch_bounds__(256, 2)
void attn_mma_kernel()
{
    extern __shared__ float sm[];
    const int tid = threadIdx.x, wid = tid >> 5, lane = tid & 31;
    const int g = lane >> 2, tg = lane & 3;
    const int qt = 15 - (int)blockIdx.x;     // heavy first
    const int bh = blockIdx.y;
    const int ktmax = 2*qt + 1;

    const int qrow_lo = qt*128 + wid*16 + g;
    const int qrow_hi = qrow_lo + 8;

    // Q fragments: 32 loads, one-time
    const float* Qb = &g_q[(size_t)(bh*SEQ)*HDIM];
    uint32_t aQ[8][4];
    #pragma unroll
    for (int ks = 0; ks < 8; ks++) {
        aQ[ks][0] = __float_as_uint(Qb[qrow_lo*64 + ks*8 + tg  ]);
        aQ[ks][1] = __float_as_uint(Qb[qrow_hi*64 + ks*8 + tg  ]);
        aQ[ks][2] = __float_as_uint(Qb[qrow_lo*64 + ks*8 + tg+4]);
        aQ[ks][3] = __float_as_uint(Qb[qrow_hi*64 + ks*8 + tg+4]);
    }

    float O[8][4];
    #pragma unroll
    for (int nj = 0; nj < 8; nj++)
        #pragma unroll
        for (int e = 0; e < 4; e++) O[nj][e] = 0.f;
    float l_lo = 0.f, l_hi = 0.f;

    const float* Kg = &g_k[(size_t)(bh*SEQ)*HDIM];
    const float* Vg = &g_v[(size_t)(bh*HDIM)*SEQ];   // [d][s]

    // FULL-tile prefetch: 64 rows x 16 float4-cols per tensor.
    auto prefetch = [&](int kt) {
        const int s = kt & 1;
        #pragma unroll
        for (int i = 0; i < 4; i++) {
            int idx = tid + 256*i;
            int row = idx >> 4, cq = idx & 15;
            cp_async16(smem_u32(sm + KS_OFF(s) + row*KST + cq*4),
                       Kg + (size_t)(kt*64 + row)*64 + cq*4);
        }
        #pragma unroll
        for (int i = 0; i < 4; i++) {
            int idx = tid + 256*i;
            int row = idx >> 4, cq = idx & 15;
            cp_async16(smem_u32(sm + VS_OFF(s) + row*KST + cq*4),
                       Vg + (size_t)row*SEQ + kt*64 + cq*4);
        }
        cp_commit();
    };

    prefetch(0);

    const int srcA = (lane & ~3) | (tg >> 1);
    const int srcB = srcA + 2;
    const bool odd = (tg & 1);

    for (int kt = 0; kt <= ktmax; kt++) {
        cp_wait<0>();
        __syncthreads();
        if (kt < ktmax) prefetch(kt + 1);

        const int jb = kt*64;
        if (jb <= qt*128 + wid*16 + 15) {   // warp-uniform: any row unmasked?
            const float* Ksm = sm + KS_OFF(kt & 1);
            const float* Vsm = sm + VS_OFF(kt & 1);

            #pragma unroll
            for (int ni = 0; ni < 8; ni++) {
                // ---- QK^T for this 8-key block ----
                float S[4] = {0.f, 0.f, 0.f, 0.f};
                const int n0 = ni*8 + g;
                #pragma unroll
                for (int ks = 0; ks < 8; ks++) {
                    uint32_t b0 = __float_as_uint(Ksm[n0*KST + ks*8 + tg  ]);
                    uint32_t b1 = __float_as_uint(Ksm[n0*KST + ks*8 + tg+4]);
                    MMA_TF32(S, aQ[ks][0], aQ[ks][1], aQ[ks][2], aQ[ks][3], b0, b1);
                }

                // ---- mask + exp (FMA pipe) + tf32 round ----
                const int j0 = jb + ni*8 + 2*tg;
                float p0 = (j0     <= qrow_lo) ? tf32r(fexp_s(S[0])) : 0.f;
                float p1 = (j0 + 1 <= qrow_lo) ? tf32r(fexp_s(S[1])) : 0.f;
                float p2 = (j0     <= qrow_hi) ? tf32r(fexp_s(S[2])) : 0.f;
                float p3 = (j0 + 1 <= qrow_hi) ? tf32r(fexp_s(S[3])) : 0.f;
                l_lo += p0 + p1;
                l_hi += p2 + p3;

                // ---- C-layout -> A-layout via intra-quad shuffles ----
                float x0, x1;
                x0 = __shfl_sync(0xFFFFFFFFu, p0, srcA);
                x1 = __shfl_sync(0xFFFFFFFFu, p1, srcA);
                uint32_t a0 = __float_as_uint(odd ? x1 : x0);   // P[g][tg]
                x0 = __shfl_sync(0xFFFFFFFFu, p2, srcA);
                x1 = __shfl_sync(0xFFFFFFFFu, p3, srcA);
                uint32_t a1 = __float_as_uint(odd ? x1 : x0);   // P[g+8][tg]
                x0 = __shfl_sync(0xFFFFFFFFu, p0, srcB);
                x1 = __shfl_sync(0xFFFFFFFFu, p1, srcB);
                uint32_t a2 = __float_as_uint(odd ? x1 : x0);   // P[g][tg+4]
                x0 = __shfl_sync(0xFFFFFFFFu, p2, srcB);
                x1 = __shfl_sync(0xFFFFFFFFu, p3, srcB);
                uint32_t a3 = __float_as_uint(odd ? x1 : x0);   // P[g+8][tg+4]

                // ---- P @ V for this 8-key block ----
                #pragma unroll
                for (int nj = 0; nj < 8; nj++) {
                    const int m0 = nj*8 + g;
                    uint32_t b0 = __float_as_uint(Vsm[m0*KST + ni*8 + tg  ]);
                    uint32_t b1 = __float_as_uint(Vsm[m0*KST + ni*8 + tg+4]);
                    MMA_TF32(O[nj], a0, a1, a2, a3, b0, b1);
                }
            }
        }
    }

    // ---- epilogue: normalize, stage (reuse K/V smem), coalesced write ----
    l_lo += __shfl_xor_sync(0xFFFFFFFFu, l_lo, 1);
    l_lo += __shfl_xor_sync(0xFFFFFFFFu, l_lo, 2);
    l_hi += __shfl_xor_sync(0xFFFFFFFFu, l_hi, 1);
    l_hi += __shfl_xor_sync(0xFFFFFFFFu, l_hi, 2);
    const float inv_lo = 1.0f / l_lo;
    const float inv_hi = 1.0f / l_hi;

    __syncthreads();   // all warps done reading K/V smem
    float* Ow = sm + wid*1088;   // [16][KST] per warp, inside K/V region
    #pragma unroll
    for (int nj = 0; nj < 8; nj++) {
        const int c0 = nj*8 + 2*tg;
        *(float2*)&Ow[ g   *KST + c0] = make_float2(O[nj][0]*inv_lo, O[nj][1]*inv_lo);
        *(float2*)&Ow[(g+8)*KST + c0] = make_float2(O[nj][2]*inv_hi, O[nj][3]*inv_hi);
    }
    __syncthreads();

    const int r = tid >> 1, half = tid & 1;
    const float* src = sm + (r >> 4)*1088 + (r & 15)*KST + half*32;
    const int grow = qt*128 + r;
    const int b = bh >> 4, h = bh & 15;
    float* dst = &g_ao[((size_t)(b*SEQ + grow))*HID + h*64 + half*32];
    #pragma unroll
    for (int e = 0; e < 8; e++) {
        float4 v = *(const float4*)&src[e*4];
        v.x = tf32r(v.x); v.y = tf32r(v.y); v.z = tf32r(v.z); v.w = tf32r(v.w);
        ((float4*)dst)[e] = v;
    }
}

// ============================================================================
// launch
// ============================================================================
extern "C" void kernel_launch(void* const* d_in, const int* in_sizes, int n_in,
                              void* d_out, int out_size)
{
    const float* X      = (const float*)d_in[0];
    const float* W_attn = (const float*)d_in[1];
    const float* b_attn = (const float*)d_in[2];
    const float* W_proj = (const float*)d_in[3];
    const float* b_proj = (const float*)d_in[4];
    const float* qg     = (const float*)d_in[5];
    const float* qb     = (const float*)d_in[6];
    const float* kg     = (const float*)d_in[7];
    const float* kb     = (const float*)d_in[8];
    float* out = (float*)d_out;

    cudaFuncSetAttribute(gemm_mma_kernel,
                         cudaFuncAttributeMaxDynamicSharedMemorySize, DYN_SMEM);
    cudaFuncSetAttribute(attn_mma_kernel,
                         cudaFuncAttributeMaxDynamicSharedMemorySize, ATT_SMEM);

    float* wtA; cudaGetSymbolAddress((void**)&wtA, g_wtA);
    float* wtP; cudaGetSymbolAddress((void**)&wtP, g_wtP);
    float* xc;  cudaGetSymbolAddress((void**)&xc,  g_xc);
    float* ao;  cudaGetSymbolAddress((void**)&ao,  g_ao);

    cvt_tf32_kernel<<<MTOT*HID/1024, 256>>>(X, xc);
    transpose_kernel<<<dim3(QKV_N/32, HID/32), dim3(32,8)>>>(W_attn, wtA, HID, QKV_N);
    transpose_kernel<<<dim3(HID/32,  HID/32), dim3(32,8)>>>(W_proj, wtP, HID, HID);

    gemm_mma_kernel<<<dim3(QKV_N/128, MTOT/128), 256, DYN_SMEM>>>(
        xc, wtA, b_attn, qg, qb, kg, kb, nullptr, QKV_N, 1);

    attn_mma_kernel<<<dim3(16, BATCH*NHEADS), 256, ATT_SMEM>>>();

    gemm_mma_kernel<<<dim3(HID/128, MTOT/128), 256, DYN_SMEM>>>(
        ao, wtP, b_proj, qg, qb, kg, kb, out, HID, 0);
}